// round 2
// baseline (speedup 1.0000x reference)
#include <cuda_runtime.h>

// Problem constants (fixed by the reference setup)
#define TOKENS 2048   // B*T = 2*1024
#define DDIM   1024   // D
#define PDIM   32     // pattern_dim
#define NPAT   256    // n_patterns
#define TOPK   4
#define NT     256    // threads per block (routing)
#define ESPLIT 2      // blocks per expert in the expert kernel
#define NPAIRS (TOKENS * TOPK)

// ---------------- global scratch (allocation-free) ----------------
__device__ int   g_count[NPAT];                 // tokens routed per expert
__device__ int   g_list[NPAT * TOKENS];         // pair ids per expert (2 MB)
__device__ float g_wt[NPAIRS];                  // scale * softmax weight
__device__ float g_proj[NPAIRS * PDIM];         // wt * silu(x @ Vd)  (1 MB)

__device__ __forceinline__ float my_silu(float z) {
    return z / (1.0f + __expf(-z));
}

// ---------------- kernel 0: zero the per-expert counters ----------------
__global__ void zero_counts_kernel() {
    g_count[threadIdx.x] = 0;
}

// ---------------- kernel 1: routing (top-4 + softmax) + out = x ----------------
__global__ __launch_bounds__(NT, 4)
void routing_kernel(const float* __restrict__ x,     // [2048,1024]
                    const float* __restrict__ hw,    // [32,1024]
                    const float* __restrict__ keys,  // [256,32]
                    const float* __restrict__ scale, // [1]
                    float* __restrict__ out)         // [2048,1024]
{
    __shared__ float sx[DDIM];
    __shared__ float sh[PDIM];
    __shared__ float ssim[NPAT];
    __shared__ float swv[TOPK];
    __shared__ int   sidxk[TOPK];
    __shared__ float rval[NT / 32];
    __shared__ int   ridx[NT / 32];

    const int tok  = blockIdx.x;
    const int t    = threadIdx.x;
    const int lane = t & 31;
    const int warp = t >> 5;

    // load x into smem
    const float* xr = x + (size_t)tok * DDIM;
    for (int i = t; i < DDIM / 4; i += NT)
        ((float4*)sx)[i] = ((const float4*)xr)[i];
    __syncthreads();

    // h[p] = x . hw[p]
    #pragma unroll
    for (int pp = 0; pp < 4; pp++) {
        const int p = warp + pp * 8;
        const float* wr = hw + (size_t)p * DDIM;
        float acc = 0.0f;
        for (int d = lane; d < DDIM; d += 32)
            acc += sx[d] * wr[d];
        #pragma unroll
        for (int o = 16; o; o >>= 1)
            acc += __shfl_xor_sync(0xFFFFFFFFu, acc, o);
        if (lane == 0) sh[p] = acc;
    }
    __syncthreads();

    // sim[n] = h . keys[n]
    {
        const float* kr = keys + (size_t)t * PDIM;
        float acc = 0.0f;
        #pragma unroll
        for (int p = 0; p < PDIM; p++)
            acc += sh[p] * kr[p];
        ssim[t] = acc;
    }
    __syncthreads();

    // top-4 (deterministic, tie-break lower index — matches lax.top_k)
    for (int k = 0; k < TOPK; k++) {
        float v  = ssim[t];
        int   id = t;
        #pragma unroll
        for (int o = 16; o; o >>= 1) {
            float ov = __shfl_xor_sync(0xFFFFFFFFu, v, o);
            int   oi = __shfl_xor_sync(0xFFFFFFFFu, id, o);
            if (ov > v || (ov == v && oi < id)) { v = ov; id = oi; }
        }
        if (lane == 0) { rval[warp] = v; ridx[warp] = id; }
        __syncthreads();
        if (t == 0) {
            float bv = rval[0]; int bi = ridx[0];
            #pragma unroll
            for (int w = 1; w < NT / 32; w++) {
                if (rval[w] > bv || (rval[w] == bv && ridx[w] < bi)) {
                    bv = rval[w]; bi = ridx[w];
                }
            }
            swv[k] = bv; sidxk[k] = bi;
            ssim[bi] = -1e30f;
        }
        __syncthreads();
    }

    // softmax over top-4 (fold scale into the weight)
    if (t == 0) {
        float m = swv[0];
        #pragma unroll
        for (int k = 1; k < TOPK; k++) m = fmaxf(m, swv[k]);
        float e[TOPK], s = 0.0f;
        #pragma unroll
        for (int k = 0; k < TOPK; k++) { e[k] = __expf(swv[k] - m); s += e[k]; }
        const float inv = scale[0] / s;
        #pragma unroll
        for (int k = 0; k < TOPK; k++) swv[k] = e[k] * inv;
    }
    __syncthreads();

    // publish routing: pair = tok*4 + k
    if (t < TOPK) {
        const int k    = t;
        const int e    = sidxk[k];
        const int pair = (tok << 2) | k;
        g_wt[pair] = swv[k];
        int slot = atomicAdd(&g_count[e], 1);
        g_list[e * TOKENS + slot] = pair;
    }

    // out = x (expert kernel accumulates on top)
    float* orow = out + (size_t)tok * DDIM;
    for (int i = t; i < DDIM / 4; i += NT)
        ((float4*)orow)[i] = ((const float4*)sx)[i];
}

// ---------------- kernel 2: per-expert compute ----------------
// grid = NPAT * ESPLIT blocks, 256 threads, 128 KB dynamic smem.
// Phase A: proj = wt * silu(x @ Vd)  (Vd in smem) -> g_proj
// Phase B: out += proj @ Vu          (Vu in smem) via atomicAdd
__global__ __launch_bounds__(256, 1)
void expert_kernel(const float* __restrict__ x,   // [2048,1024]
                   const float* __restrict__ vd,  // [256,1024,32]
                   const float* __restrict__ vu,  // [256,32,1024]
                   float* __restrict__ out)       // [2048,1024]
{
    extern __shared__ float sm[];   // 32768 floats = 128 KB

    const int e = blockIdx.x / ESPLIT;
    const int s = blockIdx.x % ESPLIT;
    const int n = g_count[e];
    const int chunk = (n + ESPLIT - 1) / ESPLIT;
    const int i0 = s * chunk;
    const int i1 = min(n, i0 + chunk);
    if (i0 >= i1) return;

    const int t    = threadIdx.x;
    const int lane = t & 31;
    const int warp = t >> 5;
    const int tok2 = lane >> 3;   // 0..3 : token within group of 4
    const int pg   = lane & 7;    // 0..7 : float4 column group

    // ---- load Vd[e] (128 KB) into smem ----
    {
        const float4* src = (const float4*)(vd + (size_t)e * DDIM * PDIM);
        float4* dst = (float4*)sm;
        for (int i = t; i < DDIM * PDIM / 4; i += 256)
            dst[i] = src[i];
    }
    __syncthreads();

    // ---- phase A: each warp processes groups of 4 tokens over full D ----
    for (int g = i0 + warp * 4; g < i1; g += 32) {
        const int  idx   = g + tok2;
        const bool valid = idx < i1;
        const int  pair  = g_list[e * TOKENS + (valid ? idx : g)];
        const int  token = pair >> 2;
        const float* xr  = x + (size_t)token * DDIM;

        float4 acc = make_float4(0.f, 0.f, 0.f, 0.f);
        #pragma unroll 2
        for (int d = 0; d < DDIM; d += 4) {
            const float4 xv = *(const float4*)(xr + d);  // L1-hot after first line
            {
                const float4 v = ((const float4*)(sm + (size_t)(d + 0) * PDIM))[pg];
                acc.x += xv.x * v.x; acc.y += xv.x * v.y; acc.z += xv.x * v.z; acc.w += xv.x * v.w;
            }
            {
                const float4 v = ((const float4*)(sm + (size_t)(d + 1) * PDIM))[pg];
                acc.x += xv.y * v.x; acc.y += xv.y * v.y; acc.z += xv.y * v.z; acc.w += xv.y * v.w;
            }
            {
                const float4 v = ((const float4*)(sm + (size_t)(d + 2) * PDIM))[pg];
                acc.x += xv.z * v.x; acc.y += xv.z * v.y; acc.z += xv.z * v.z; acc.w += xv.z * v.w;
            }
            {
                const float4 v = ((const float4*)(sm + (size_t)(d + 3) * PDIM))[pg];
                acc.x += xv.w * v.x; acc.y += xv.w * v.y; acc.z += xv.w * v.z; acc.w += xv.w * v.w;
            }
        }
        if (valid) {
            const float wt = g_wt[pair];
            float4 o;
            o.x = wt * my_silu(acc.x);
            o.y = wt * my_silu(acc.y);
            o.z = wt * my_silu(acc.z);
            o.w = wt * my_silu(acc.w);
            ((float4*)(g_proj + (size_t)pair * PDIM))[pg] = o;
        }
    }
    __syncthreads();

    // ---- load Vu[e] (128 KB) into smem ----
    {
        const float4* src = (const float4*)(vu + (size_t)e * PDIM * DDIM);
        float4* dst = (float4*)sm;
        for (int i = t; i < DDIM * PDIM / 4; i += 256)
            dst[i] = src[i];
    }
    __syncthreads();

    // ---- phase B: out[token] += proj @ Vu ----
    const int dg = pg;  // 0..7 : float4 group within a 32-wide d chunk
    for (int g = i0 + warp * 4; g < i1; g += 32) {
        const int  idx   = g + tok2;
        const bool valid = idx < i1;
        const int  pair  = g_list[e * TOKENS + (valid ? idx : g)];
        const int  token = pair >> 2;

        // hoist proj (32 floats, already weight-scaled) into registers
        float pj[PDIM];
        {
            const float4* pr = (const float4*)(g_proj + (size_t)pair * PDIM);
            #pragma unroll
            for (int i = 0; i < PDIM / 4; i++) {
                const float4 v = pr[i];
                pj[i * 4 + 0] = v.x; pj[i * 4 + 1] = v.y;
                pj[i * 4 + 2] = v.z; pj[i * 4 + 3] = v.w;
            }
        }

        float* orow = out + (size_t)token * DDIM;
        for (int pass = 0; pass < DDIM / 32; pass++) {
            const int dbase = pass * 32 + dg * 4;
            float4 acc = make_float4(0.f, 0.f, 0.f, 0.f);
            #pragma unroll
            for (int p = 0; p < PDIM; p++) {
                const float4 v = *(const float4*)(sm + (size_t)p * DDIM + dbase);
                acc.x += pj[p] * v.x; acc.y += pj[p] * v.y;
                acc.z += pj[p] * v.z; acc.w += pj[p] * v.w;
            }
            if (valid) {
                atomicAdd(orow + dbase + 0, acc.x);
                atomicAdd(orow + dbase + 1, acc.y);
                atomicAdd(orow + dbase + 2, acc.z);
                atomicAdd(orow + dbase + 3, acc.w);
            }
        }
    }
}

// ---------------- launch ----------------
extern "C" void kernel_launch(void* const* d_in, const int* in_sizes, int n_in,
                              void* d_out, int out_size) {
    const float* x     = (const float*)d_in[0];
    const float* hw    = (const float*)d_in[1];
    const float* keys  = (const float*)d_in[2];
    const float* vd    = (const float*)d_in[3];
    const float* vu    = (const float*)d_in[4];
    const float* scale = (const float*)d_in[5];
    float* out = (float*)d_out;

    const int smem_bytes = DDIM * PDIM * (int)sizeof(float);  // 128 KB
    cudaFuncSetAttribute(expert_kernel,
                         cudaFuncAttributeMaxDynamicSharedMemorySize, smem_bytes);

    zero_counts_kernel<<<1, NPAT>>>();
    routing_kernel<<<TOKENS, NT>>>(x, hw, keys, scale, out);
    expert_kernel<<<NPAT * ESPLIT, 256, smem_bytes>>>(x, vd, vu, out);
}